// round 9
// baseline (speedup 1.0000x reference)
#include <cuda_runtime.h>
#include <cuda_bf16.h>
#include <cstdint>

#define D 128
#define NMAX 50176
#define EMAX 800000
#define N_LAYERS 4

// ---------------- device scratch (allocation-free rule) ----------------
__device__ int   g_deg_out[NMAX];
__device__ int   g_deg_in[NMAX];
__device__ float g_norm_src[NMAX];
__device__ float g_norm_dst[NMAX];
__device__ int   g_row_ptr[NMAX + 1];
__device__ int   g_cursor[NMAX];
__device__ int   g_col[EMAX];
__device__ __align__(16) float g_h0[NMAX * D];
__device__ __align__(16) float g_h1[NMAX * D];
// W in mma-fragment layout: [layer][frag(128)][lane(32)] = {hi0,hi1,lo0,lo1}
__device__ __align__(16) uint4 g_wfrag[N_LAYERS * 128 * 32];

// ---------------- setup kernels ----------------
__global__ void k_zero(int n) {
    int i = blockIdx.x * blockDim.x + threadIdx.x;
    if (i < n) { g_deg_out[i] = 0; g_deg_in[i] = 0; }
}

__global__ void k_count(const int* __restrict__ src, const int* __restrict__ dst, int e) {
    int i = blockIdx.x * blockDim.x + threadIdx.x;
    if (i < e) {
        atomicAdd(&g_deg_out[src[i]], 1);
        atomicAdd(&g_deg_in[dst[i]], 1);
    }
}

// scan of in-degrees -> row_ptr/cursor, plus both norm vectors (single block)
__global__ void k_scan(int n) {
    __shared__ int warp_sums[32];
    int t = threadIdx.x, lane = t & 31, wid = t >> 5;
    int chunk = (n + 1023) >> 10;
    int start = t * chunk;
    int end = min(start + chunk, n);
    int local = 0;
    for (int i = start; i < end; i++) {
        int di = g_deg_in[i];
        local += di;
        g_norm_dst[i] = rsqrtf(fmaxf((float)di, 1.0f));
        g_norm_src[i] = rsqrtf(fmaxf((float)g_deg_out[i], 1.0f));
    }
    int x = local;
    #pragma unroll
    for (int off = 1; off < 32; off <<= 1) {
        int y = __shfl_up_sync(0xffffffffu, x, off);
        if (lane >= off) x += y;
    }
    if (lane == 31) warp_sums[wid] = x;
    __syncthreads();
    if (wid == 0) {
        int s = warp_sums[lane];
        #pragma unroll
        for (int off = 1; off < 32; off <<= 1) {
            int y = __shfl_up_sync(0xffffffffu, s, off);
            if (lane >= off) s += y;
        }
        warp_sums[lane] = s;
    }
    __syncthreads();
    int run = x - local + (wid > 0 ? warp_sums[wid - 1] : 0);
    for (int i = start; i < end; i++) {
        int v = g_deg_in[i];
        g_row_ptr[i] = run;
        g_cursor[i] = run;
        run += v;
    }
    if (t == 0) g_row_ptr[n] = warp_sums[31];
}

__global__ void k_fill(const int* __restrict__ src, const int* __restrict__ dst, int e) {
    int i = blockIdx.x * blockDim.x + threadIdx.x;
    if (i < e) {
        int p = atomicAdd(&g_cursor[dst[i]], 1);
        g_col[p] = src[i];
    }
}

// Build W fragments (B operand of m16n8k16, col layout), hi/lo bf16 split.
__global__ void k_prep_w(const float* __restrict__ W) {
    int idx = blockIdx.x * blockDim.x + threadIdx.x;   // 4*8*16*32 = 16384
    if (idx >= N_LAYERS * 8 * 16 * 32) return;
    int lane = idx & 31;
    int nfg  = (idx >> 5) & 15;
    int ks   = (idx >> 9) & 7;
    int l    = idx >> 12;
    int c  = nfg * 8 + (lane >> 2);
    int rk = ks * 16 + (lane & 3) * 2;
    const float* Wl = W + (size_t)l * D * D;
    float w00 = Wl[rk * D + c];
    float w01 = Wl[(rk + 1) * D + c];
    float w10 = Wl[(rk + 8) * D + c];
    float w11 = Wl[(rk + 9) * D + c];
    __nv_bfloat162 h, lo;
    uint4 out;
    h.x = __float2bfloat16_rn(w00); h.y = __float2bfloat16_rn(w01);
    lo.x = __float2bfloat16_rn(w00 - __bfloat162float(h.x));
    lo.y = __float2bfloat16_rn(w01 - __bfloat162float(h.y));
    out.x = *(uint32_t*)&h;
    out.z = *(uint32_t*)&lo;
    h.x = __float2bfloat16_rn(w10); h.y = __float2bfloat16_rn(w11);
    lo.x = __float2bfloat16_rn(w10 - __bfloat162float(h.x));
    lo.y = __float2bfloat16_rn(w11 - __bfloat162float(h.y));
    out.y = *(uint32_t*)&h;
    out.w = *(uint32_t*)&lo;
    g_wfrag[((size_t)l * 128 + ks * 16 + nfg) * 32 + lane] = out;
}

// ---------------- fused layer: aggregate(128 rows) -> smem frags -> mma GEMM ----------------
__device__ __forceinline__ void mma16816(float* d, const uint32_t* a, uint32_t b0, uint32_t b1) {
    asm volatile(
        "mma.sync.aligned.m16n8k16.row.col.f32.bf16.bf16.f32 "
        "{%0,%1,%2,%3}, {%4,%5,%6,%7}, {%8,%9}, {%0,%1,%2,%3};"
        : "+f"(d[0]), "+f"(d[1]), "+f"(d[2]), "+f"(d[3])
        : "r"(a[0]), "r"(a[1]), "r"(a[2]), "r"(a[3]), "r"(b0), "r"(b1));
}

// smem: frag_hi [8 groups][8 ks][32 lanes][4 regs] u32 = 32KB, frag_lo same. 64KB total.
#define SMEM_BYTES 65536

__global__ void __launch_bounds__(256)
k_layer(const float* __restrict__ hin, const uint4* __restrict__ wfrag,
        const float* __restrict__ bias, float* __restrict__ C, int n) {
    extern __shared__ __align__(16) uint32_t smem[];
    uint32_t* fh = smem;            // 8192 u32
    uint32_t* fl = smem + 8192;
    int tid = threadIdx.x;
    int warp = tid >> 5, lane = tid & 31;
    int m0 = blockIdx.x * 128;

    // ---- Phase 1: aggregation. Warp w handles rows group w (16 rows). ----
    const float4* h4 = (const float4*)hin;
    #pragma unroll 1
    for (int p = 0; p < 16; p++) {
        int row = m0 + warp * 16 + p;
        float4 acc = make_float4(0.f, 0.f, 0.f, 0.f);
        if (row < n) {
            int j0 = g_row_ptr[row];
            int j1 = g_row_ptr[row + 1];
            for (int j = j0; j < j1; j++) {
                int s = g_col[j];
                float ns = g_norm_src[s];
                float4 v = __ldg(&h4[(size_t)s * 32 + lane]);
                acc.x = fmaf(ns, v.x, acc.x);
                acc.y = fmaf(ns, v.y, acc.y);
                acc.z = fmaf(ns, v.z, acc.z);
                acc.w = fmaf(ns, v.w, acc.w);
            }
            float nd = g_norm_dst[row];
            acc.x *= nd; acc.y *= nd; acc.z *= nd; acc.w *= nd;
        }
        // hi/lo bf16 split, packed pairs: q0 = 2*lane (dims 4l,4l+1), q1 = 2*lane+1
        __nv_bfloat162 h01, h23, l01, l23;
        h01.x = __float2bfloat16_rn(acc.x); h01.y = __float2bfloat16_rn(acc.y);
        h23.x = __float2bfloat16_rn(acc.z); h23.y = __float2bfloat16_rn(acc.w);
        l01.x = __float2bfloat16_rn(acc.x - __bfloat162float(h01.x));
        l01.y = __float2bfloat16_rn(acc.y - __bfloat162float(h01.y));
        l23.x = __float2bfloat16_rn(acc.z - __bfloat162float(h23.x));
        l23.y = __float2bfloat16_rn(acc.w - __bfloat162float(h23.y));
        int q0 = lane * 2, q1 = q0 + 1;
        int ks0 = q0 >> 3, j0q = q0 & 7;
        int ks1 = q1 >> 3, j1q = q1 & 7;
        int i0 = ((warp * 8 + ks0) * 32 + (((p & 7) << 2) | (j0q & 3))) * 4 + (p >> 3) + ((j0q >> 2) << 1);
        int i1 = ((warp * 8 + ks1) * 32 + (((p & 7) << 2) | (j1q & 3))) * 4 + (p >> 3) + ((j1q >> 2) << 1);
        fh[i0] = *(uint32_t*)&h01; fh[i1] = *(uint32_t*)&h23;
        fl[i0] = *(uint32_t*)&l01; fl[i1] = *(uint32_t*)&l23;
    }
    __syncthreads();

    // ---- Phase 2: GEMM. 8 warps: 4 (M, 32 rows) x 2 (N, 64 cols). ----
    int warp_m = warp & 3, warp_n = warp >> 2;
    int r0 = lane >> 2;
    int cp = lane & 3;
    float d[2][8][4];
    #pragma unroll
    for (int mf = 0; mf < 2; mf++)
        #pragma unroll
        for (int nf = 0; nf < 8; nf++)
            #pragma unroll
            for (int j = 0; j < 4; j++) d[mf][nf][j] = 0.f;

    const uint4* fh4 = (const uint4*)fh;
    const uint4* fl4 = (const uint4*)fl;
    #pragma unroll
    for (int ks = 0; ks < 8; ks++) {
        uint4 AH[2], AL[2];
        #pragma unroll
        for (int mf = 0; mf < 2; mf++) {
            int g = warp_m * 2 + mf;
            AH[mf] = fh4[(g * 8 + ks) * 32 + lane];
            AL[mf] = fl4[(g * 8 + ks) * 32 + lane];
        }
        #pragma unroll
        for (int nf = 0; nf < 8; nf++) {
            uint4 w = __ldg(&wfrag[((size_t)ks * 16 + warp_n * 8 + nf) * 32 + lane]);
            #pragma unroll
            for (int mf = 0; mf < 2; mf++) {
                mma16816(d[mf][nf], (const uint32_t*)&AH[mf], w.x, w.y);  // hi*hi
                mma16816(d[mf][nf], (const uint32_t*)&AH[mf], w.z, w.w);  // hi*lo
                mma16816(d[mf][nf], (const uint32_t*)&AL[mf], w.x, w.y);  // lo*hi
            }
        }
    }

    // ---- Epilogue: bias + store ----
    int n_base = warp_n * 64;
    #pragma unroll
    for (int nf = 0; nf < 8; nf++) {
        int col = n_base + nf * 8 + cp * 2;
        float2 bb = *(const float2*)&bias[col];
        #pragma unroll
        for (int mf = 0; mf < 2; mf++) {
            int row0 = m0 + warp_m * 32 + mf * 16 + r0;
            int row1 = row0 + 8;
            if (row0 < n) {
                float2 o = make_float2(d[mf][nf][0] + bb.x, d[mf][nf][1] + bb.y);
                *(float2*)&C[(size_t)row0 * 128 + col] = o;
            }
            if (row1 < n) {
                float2 o = make_float2(d[mf][nf][2] + bb.x, d[mf][nf][3] + bb.y);
                *(float2*)&C[(size_t)row1 * 128 + col] = o;
            }
        }
    }
}

// ---------------- host ----------------
extern "C" void kernel_launch(void* const* d_in, const int* in_sizes, int n_in,
                              void* d_out, int out_size) {
    const float* feat = (const float*)d_in[0];
    const float* W    = (const float*)d_in[1];
    const float* b    = (const float*)d_in[2];
    const int*   src  = (const int*)d_in[3];   // jax x64-off: int32
    const int*   dst  = (const int*)d_in[4];
    int N = in_sizes[0] / D;
    int E = in_sizes[3];

    cudaFuncSetAttribute(k_layer, cudaFuncAttributeMaxDynamicSharedMemorySize, SMEM_BYTES);

    float *h0, *h1;
    cudaGetSymbolAddress((void**)&h0, g_h0);
    cudaGetSymbolAddress((void**)&h1, g_h1);
    uint4* wfrag;
    cudaGetSymbolAddress((void**)&wfrag, g_wfrag);

    int nb = (N + 255) / 256;
    int eb = (E + 255) / 256;

    k_zero<<<nb, 256>>>(N);                                  // launch 0
    k_count<<<eb, 256>>>(src, dst, E);                        // 1
    k_scan<<<1, 1024>>>(N);                                   // 2 (scan + norms)
    k_fill<<<eb, 256>>>(src, dst, E);                         // 3
    k_prep_w<<<(N_LAYERS * 8 * 16 * 32 + 255) / 256, 256>>>(W); // 4

    float* out = (float*)d_out;
    const float* hin = feat;
    int layerBlocks = (N + 127) / 128;

    for (int l = 0; l < N_LAYERS; l++) {                      // 5,6,7,8
        float* hout = (l == N_LAYERS - 1) ? out : ((l & 1) ? h1 : h0);
        k_layer<<<layerBlocks, 256, SMEM_BYTES>>>(hin, wfrag + (size_t)l * 128 * 32,
                                                  b + (size_t)l * D, hout, N);
        hin = hout;
    }
}

// round 12
// speedup vs baseline: 1.1700x; 1.1700x over previous
#include <cuda_runtime.h>
#include <cuda_bf16.h>
#include <cstdint>

#define D 128
#define NMAX 50176
#define EMAX 800000
#define N_LAYERS 4

// ---------------- device scratch (allocation-free rule) ----------------
__device__ int   g_deg_out[NMAX];
__device__ int   g_deg_in[NMAX];
__device__ float g_norm_src[NMAX];
__device__ float g_norm_dst[NMAX];
__device__ int   g_row_ptr[NMAX + 1];
__device__ int   g_cursor[NMAX];
__device__ int   g_col[EMAX];
__device__ __align__(16) float    g_h0[NMAX * D];
__device__ __align__(16) float    g_h1[NMAX * D];
// Aggregated features, bf16 hi/lo packed pairs, PERMUTED within each ks-group
// (order 0,4,1,5,2,6,3,7) so GEMM fragment regs (a0,a2)/(a1,a3) are uint2-contiguous.
__device__ __align__(16) uint32_t g_agg_hi[NMAX * 64];
__device__ __align__(16) uint32_t g_agg_lo[NMAX * 64];
// W in mma-fragment layout: [layer][frag(128)][lane(32)] = {hi0,hi1,lo0,lo1}
__device__ __align__(16) uint4    g_wfrag[N_LAYERS * 128 * 32];

// ---------------- setup kernels ----------------
__global__ void k_zero(int n) {
    int i = blockIdx.x * blockDim.x + threadIdx.x;
    if (i < n) { g_deg_out[i] = 0; g_deg_in[i] = 0; }
}

// 4 edges per thread (int4 loads) for MLP
__global__ void k_count(const int* __restrict__ src, const int* __restrict__ dst, int e) {
    int i4 = blockIdx.x * blockDim.x + threadIdx.x;
    int base = i4 * 4;
    if (base + 3 < e) {
        int4 s = *(const int4*)&src[base];
        int4 t = *(const int4*)&dst[base];
        atomicAdd(&g_deg_out[s.x], 1);
        atomicAdd(&g_deg_out[s.y], 1);
        atomicAdd(&g_deg_out[s.z], 1);
        atomicAdd(&g_deg_out[s.w], 1);
        atomicAdd(&g_deg_in[t.x], 1);
        atomicAdd(&g_deg_in[t.y], 1);
        atomicAdd(&g_deg_in[t.z], 1);
        atomicAdd(&g_deg_in[t.w], 1);
    } else {
        for (int i = base; i < e; i++) {
            atomicAdd(&g_deg_out[src[i]], 1);
            atomicAdd(&g_deg_in[dst[i]], 1);
        }
    }
}

// scan of in-degrees -> row_ptr/cursor, plus both norm vectors (single block)
__global__ void k_scan(int n) {
    __shared__ int warp_sums[32];
    int t = threadIdx.x, lane = t & 31, wid = t >> 5;
    int chunk = (n + 1023) >> 10;
    int start = t * chunk;
    int end = min(start + chunk, n);
    int local = 0;
    for (int i = start; i < end; i++) {
        int di = g_deg_in[i];
        local += di;
        g_norm_dst[i] = rsqrtf(fmaxf((float)di, 1.0f));
        g_norm_src[i] = rsqrtf(fmaxf((float)g_deg_out[i], 1.0f));
    }
    int x = local;
    #pragma unroll
    for (int off = 1; off < 32; off <<= 1) {
        int y = __shfl_up_sync(0xffffffffu, x, off);
        if (lane >= off) x += y;
    }
    if (lane == 31) warp_sums[wid] = x;
    __syncthreads();
    if (wid == 0) {
        int s = warp_sums[lane];
        #pragma unroll
        for (int off = 1; off < 32; off <<= 1) {
            int y = __shfl_up_sync(0xffffffffu, s, off);
            if (lane >= off) s += y;
        }
        warp_sums[lane] = s;
    }
    __syncthreads();
    int run = x - local + (wid > 0 ? warp_sums[wid - 1] : 0);
    for (int i = start; i < end; i++) {
        int v = g_deg_in[i];
        g_row_ptr[i] = run;
        g_cursor[i] = run;
        run += v;
    }
    if (t == 0) g_row_ptr[n] = warp_sums[31];
}

__global__ void k_fill(const int* __restrict__ src, const int* __restrict__ dst, int e) {
    int i4 = blockIdx.x * blockDim.x + threadIdx.x;
    int base = i4 * 4;
    if (base + 3 < e) {
        int4 s = *(const int4*)&src[base];
        int4 t = *(const int4*)&dst[base];
        g_col[atomicAdd(&g_cursor[t.x], 1)] = s.x;
        g_col[atomicAdd(&g_cursor[t.y], 1)] = s.y;
        g_col[atomicAdd(&g_cursor[t.z], 1)] = s.z;
        g_col[atomicAdd(&g_cursor[t.w], 1)] = s.w;
    } else {
        for (int i = base; i < e; i++)
            g_col[atomicAdd(&g_cursor[dst[i]], 1)] = src[i];
    }
}

// Build W fragments (B operand of m16n8k16, col layout), hi/lo bf16 split.
__global__ void k_prep_w(const float* __restrict__ W) {
    int idx = blockIdx.x * blockDim.x + threadIdx.x;   // 4*8*16*32 = 16384
    if (idx >= N_LAYERS * 8 * 16 * 32) return;
    int lane = idx & 31;
    int nfg  = (idx >> 5) & 15;
    int ks   = (idx >> 9) & 7;
    int l    = idx >> 12;
    int c  = nfg * 8 + (lane >> 2);
    int rk = ks * 16 + (lane & 3) * 2;
    const float* Wl = W + (size_t)l * D * D;
    float w00 = Wl[rk * D + c];
    float w01 = Wl[(rk + 1) * D + c];
    float w10 = Wl[(rk + 8) * D + c];
    float w11 = Wl[(rk + 9) * D + c];
    __nv_bfloat162 h, lo;
    uint4 out;
    h.x = __float2bfloat16_rn(w00); h.y = __float2bfloat16_rn(w01);
    lo.x = __float2bfloat16_rn(w00 - __bfloat162float(h.x));
    lo.y = __float2bfloat16_rn(w01 - __bfloat162float(h.y));
    out.x = *(uint32_t*)&h;
    out.z = *(uint32_t*)&lo;
    h.x = __float2bfloat16_rn(w10); h.y = __float2bfloat16_rn(w11);
    lo.x = __float2bfloat16_rn(w10 - __bfloat162float(h.x));
    lo.y = __float2bfloat16_rn(w11 - __bfloat162float(h.y));
    out.y = *(uint32_t*)&h;
    out.w = *(uint32_t*)&lo;
    g_wfrag[((size_t)l * 128 + ks * 16 + nfg) * 32 + lane] = out;
}

// permuted storage position of global pair index q (0..63):
// ks = q>>3; pos-in-group = (q&3)*2 + ((q>>2)&1)
__device__ __forceinline__ int pair_slot(int q) {
    return ((q >> 3) << 3) + ((q & 3) * 2) + ((q >> 2) & 1);
}

// ---------------- aggregation: warp per node, writes permuted bf16 hi/lo pairs ----------------
__global__ void k_agg(const float* __restrict__ hin, int n) {
    int w = (blockIdx.x * blockDim.x + threadIdx.x) >> 5;
    int lane = threadIdx.x & 31;
    if (w >= n) return;
    int j0 = g_row_ptr[w];
    int j1 = g_row_ptr[w + 1];
    const float4* h4 = (const float4*)hin;
    float4 acc = make_float4(0.f, 0.f, 0.f, 0.f);
    int j = j0;
    for (; j + 1 < j1; j += 2) {          // 2-way unroll for MLP
        int s0 = g_col[j];
        int s1 = g_col[j + 1];
        float ns0 = g_norm_src[s0];
        float ns1 = g_norm_src[s1];
        float4 v0 = __ldg(&h4[(size_t)s0 * 32 + lane]);
        float4 v1 = __ldg(&h4[(size_t)s1 * 32 + lane]);
        acc.x = fmaf(ns0, v0.x, acc.x); acc.y = fmaf(ns0, v0.y, acc.y);
        acc.z = fmaf(ns0, v0.z, acc.z); acc.w = fmaf(ns0, v0.w, acc.w);
        acc.x = fmaf(ns1, v1.x, acc.x); acc.y = fmaf(ns1, v1.y, acc.y);
        acc.z = fmaf(ns1, v1.z, acc.z); acc.w = fmaf(ns1, v1.w, acc.w);
    }
    if (j < j1) {
        int s = g_col[j];
        float ns = g_norm_src[s];
        float4 v = __ldg(&h4[(size_t)s * 32 + lane]);
        acc.x = fmaf(ns, v.x, acc.x); acc.y = fmaf(ns, v.y, acc.y);
        acc.z = fmaf(ns, v.z, acc.z); acc.w = fmaf(ns, v.w, acc.w);
    }
    float nd = g_norm_dst[w];
    float ox = acc.x * nd, oy = acc.y * nd, oz = acc.z * nd, ow = acc.w * nd;
    __nv_bfloat162 h01, h23, l01, l23;
    h01.x = __float2bfloat16_rn(ox); h01.y = __float2bfloat16_rn(oy);
    h23.x = __float2bfloat16_rn(oz); h23.y = __float2bfloat16_rn(ow);
    l01.x = __float2bfloat16_rn(ox - __bfloat162float(h01.x));
    l01.y = __float2bfloat16_rn(oy - __bfloat162float(h01.y));
    l23.x = __float2bfloat16_rn(oz - __bfloat162float(h23.x));
    l23.y = __float2bfloat16_rn(ow - __bfloat162float(h23.y));
    int q0 = lane * 2, q1 = q0 + 1;
    size_t base = (size_t)w * 64;
    g_agg_hi[base + pair_slot(q0)] = *(uint32_t*)&h01;
    g_agg_hi[base + pair_slot(q1)] = *(uint32_t*)&h23;
    g_agg_lo[base + pair_slot(q0)] = *(uint32_t*)&l01;
    g_agg_lo[base + pair_slot(q1)] = *(uint32_t*)&l23;
}

// ---------------- GEMM via mma.sync bf16 (hi/lo split) ----------------
__device__ __forceinline__ void mma16816(float* d, uint32_t a0, uint32_t a1, uint32_t a2,
                                         uint32_t a3, uint32_t b0, uint32_t b1) {
    asm volatile(
        "mma.sync.aligned.m16n8k16.row.col.f32.bf16.bf16.f32 "
        "{%0,%1,%2,%3}, {%4,%5,%6,%7}, {%8,%9}, {%0,%1,%2,%3};"
        : "+f"(d[0]), "+f"(d[1]), "+f"(d[2]), "+f"(d[3])
        : "r"(a0), "r"(a1), "r"(a2), "r"(a3), "r"(b0), "r"(b1));
}

// CTA: 128 rows x 128 cols. 8 warps: 4 (M, 32 rows each) x 2 (N, 64 cols each).
__global__ void __launch_bounds__(256)
k_gemm_mma(const uint4* __restrict__ wfrag, const float* __restrict__ bias,
           float* __restrict__ C, int n) {
    int tid = threadIdx.x;
    int warp = tid >> 5, lane = tid & 31;
    int warp_m = warp & 3, warp_n = warp >> 2;
    int m_base = blockIdx.x * 128 + warp_m * 32;
    int n_base = warp_n * 64;
    int r0 = lane >> 2;          // 0..7
    int cp = lane & 3;           // col-pair index within fragment

    float d[2][8][4];
    #pragma unroll
    for (int mf = 0; mf < 2; mf++)
        #pragma unroll
        for (int nf = 0; nf < 8; nf++)
            #pragma unroll
            for (int j = 0; j < 4; j++) d[mf][nf][j] = 0.f;

    const uint2* hi2 = (const uint2*)g_agg_hi;
    const uint2* lo2 = (const uint2*)g_agg_lo;

    #pragma unroll
    for (int ks = 0; ks < 8; ks++) {
        // per mf: rows row0, row0+8; lane reads uint2 = {pair ks*8+cp, pair ks*8+cp+4}
        uint2 AH0[2], AH1[2], AL0[2], AL1[2];
        #pragma unroll
        for (int mf = 0; mf < 2; mf++) {
            int row0 = m_base + mf * 16 + r0;
            int row1 = row0 + 8;
            bool v0 = row0 < n, v1 = row1 < n;
            size_t i0 = (size_t)row0 * 32 + ks * 4 + cp;
            size_t i1 = (size_t)row1 * 32 + ks * 4 + cp;
            AH0[mf] = v0 ? __ldg(&hi2[i0]) : make_uint2(0u, 0u);
            AH1[mf] = v1 ? __ldg(&hi2[i1]) : make_uint2(0u, 0u);
            AL0[mf] = v0 ? __ldg(&lo2[i0]) : make_uint2(0u, 0u);
            AL1[mf] = v1 ? __ldg(&lo2[i1]) : make_uint2(0u, 0u);
        }
        #pragma unroll
        for (int nf = 0; nf < 8; nf++) {
            uint4 w = __ldg(&wfrag[((size_t)ks * 16 + warp_n * 8 + nf) * 32 + lane]);
            #pragma unroll
            for (int mf = 0; mf < 2; mf++) {
                mma16816(d[mf][nf], AH0[mf].x, AH1[mf].x, AH0[mf].y, AH1[mf].y, w.x, w.y); // hi*hi
                mma16816(d[mf][nf], AH0[mf].x, AH1[mf].x, AH0[mf].y, AH1[mf].y, w.z, w.w); // hi*lo
                mma16816(d[mf][nf], AL0[mf].x, AL1[mf].x, AL0[mf].y, AL1[mf].y, w.x, w.y); // lo*hi
            }
        }
    }

    // Epilogue: bias add + store
    #pragma unroll
    for (int nf = 0; nf < 8; nf++) {
        int col = n_base + nf * 8 + cp * 2;
        float2 bb = *(const float2*)&bias[col];
        #pragma unroll
        for (int mf = 0; mf < 2; mf++) {
            int row0 = m_base + mf * 16 + r0;
            int row1 = row0 + 8;
            if (row0 < n) {
                float2 o = make_float2(d[mf][nf][0] + bb.x, d[mf][nf][1] + bb.y);
                *(float2*)&C[(size_t)row0 * 128 + col] = o;
            }
            if (row1 < n) {
                float2 o = make_float2(d[mf][nf][2] + bb.x, d[mf][nf][3] + bb.y);
                *(float2*)&C[(size_t)row1 * 128 + col] = o;
            }
        }
    }
}

// ---------------- host ----------------
extern "C" void kernel_launch(void* const* d_in, const int* in_sizes, int n_in,
                              void* d_out, int out_size) {
    const float* feat = (const float*)d_in[0];
    const float* W    = (const float*)d_in[1];
    const float* b    = (const float*)d_in[2];
    const int*   src  = (const int*)d_in[3];   // jax x64-off: int32
    const int*   dst  = (const int*)d_in[4];
    int N = in_sizes[0] / D;
    int E = in_sizes[3];

    float *h0, *h1;
    cudaGetSymbolAddress((void**)&h0, g_h0);
    cudaGetSymbolAddress((void**)&h1, g_h1);
    uint4* wfrag;
    cudaGetSymbolAddress((void**)&wfrag, g_wfrag);

    int nb  = (N + 255) / 256;
    int eb4 = ((E + 3) / 4 + 255) / 256;

    k_zero<<<nb, 256>>>(N);                                       // 0
    k_count<<<eb4, 256>>>(src, dst, E);                           // 1
    k_scan<<<1, 1024>>>(N);                                       // 2 (scan + norms)
    k_fill<<<eb4, 256>>>(src, dst, E);                            // 3
    k_prep_w<<<(N_LAYERS * 8 * 16 * 32 + 255) / 256, 256>>>(W);   // 4

    float* out = (float*)d_out;
    const float* hin = feat;
    int aggBlocks  = (N + 7) / 8;
    int gemmBlocks = (N + 127) / 128;

    for (int l = 0; l < N_LAYERS; l++) {                          // 5..12
        k_agg<<<aggBlocks, 256>>>(hin, N);
        float* hout = (l == N_LAYERS - 1) ? out : ((l & 1) ? h1 : h0);
        k_gemm_mma<<<gemmBlocks, 256>>>(wfrag + (size_t)l * 128 * 32,
                                        b + (size_t)l * D, hout, N);
        hin = hout;
    }
}

// round 16
// speedup vs baseline: 1.2015x; 1.0269x over previous
#include <cuda_runtime.h>
#include <cuda_bf16.h>
#include <cstdint>

#define D 128
#define NMAX 50176
#define EMAX 800000
#define N_LAYERS 4

// ---------------- device scratch (allocation-free rule) ----------------
__device__ int   g_deg_out[NMAX];
__device__ int   g_deg_in[NMAX];
__device__ float g_norm_src[NMAX];
__device__ float g_norm_dst[NMAX];
__device__ int   g_row_ptr[NMAX + 1];
__device__ int   g_cursor[NMAX];
__device__ int   g_col[EMAX];
__device__ __align__(16) float    g_h0[NMAX * D];
__device__ __align__(16) float    g_h1[NMAX * D];
// Aggregated features, bf16 hi/lo packed pairs, PERMUTED within each ks-group
// (pos = (q&3)*2 + ((q>>2)&1)) so GEMM fragment regs (a0,a2)/(a1,a3) are uint2-contiguous.
__device__ __align__(16) uint32_t g_agg_hi[NMAX * 64];
__device__ __align__(16) uint32_t g_agg_lo[NMAX * 64];
// W in mma-fragment layout: [layer][frag(128)][lane(32)] = {hi0,hi1,lo0,lo1}
__device__ __align__(16) uint4    g_wfrag[N_LAYERS * 128 * 32];

// ---------------- setup kernels ----------------
__global__ void k_zero(int n) {
    int i = blockIdx.x * blockDim.x + threadIdx.x;
    if (i < n) { g_deg_out[i] = 0; g_deg_in[i] = 0; }
}

__global__ void k_count(const int* __restrict__ src, const int* __restrict__ dst, int e) {
    int i = blockIdx.x * blockDim.x + threadIdx.x;
    if (i < e) {
        atomicAdd(&g_deg_out[src[i]], 1);
        atomicAdd(&g_deg_in[dst[i]], 1);
    }
}

// scan of in-degrees -> row_ptr/cursor, plus both norm vectors (single block)
__global__ void k_scan(int n) {
    __shared__ int warp_sums[32];
    int t = threadIdx.x, lane = t & 31, wid = t >> 5;
    int chunk = (n + 1023) >> 10;
    int start = t * chunk;
    int end = min(start + chunk, n);
    int local = 0;
    for (int i = start; i < end; i++) {
        int di = g_deg_in[i];
        local += di;
        g_norm_dst[i] = rsqrtf(fmaxf((float)di, 1.0f));
        g_norm_src[i] = rsqrtf(fmaxf((float)g_deg_out[i], 1.0f));
    }
    int x = local;
    #pragma unroll
    for (int off = 1; off < 32; off <<= 1) {
        int y = __shfl_up_sync(0xffffffffu, x, off);
        if (lane >= off) x += y;
    }
    if (lane == 31) warp_sums[wid] = x;
    __syncthreads();
    if (wid == 0) {
        int s = warp_sums[lane];
        #pragma unroll
        for (int off = 1; off < 32; off <<= 1) {
            int y = __shfl_up_sync(0xffffffffu, s, off);
            if (lane >= off) s += y;
        }
        warp_sums[lane] = s;
    }
    __syncthreads();
    int run = x - local + (wid > 0 ? warp_sums[wid - 1] : 0);
    for (int i = start; i < end; i++) {
        int v = g_deg_in[i];
        g_row_ptr[i] = run;
        g_cursor[i] = run;
        run += v;
    }
    if (t == 0) g_row_ptr[n] = warp_sums[31];
}

__global__ void k_fill(const int* __restrict__ src, const int* __restrict__ dst, int e) {
    int i = blockIdx.x * blockDim.x + threadIdx.x;
    if (i < e) {
        int p = atomicAdd(&g_cursor[dst[i]], 1);
        g_col[p] = src[i];
    }
}

// Build W fragments (B operand of m16n8k16, col layout), hi/lo bf16 split.
__global__ void k_prep_w(const float* __restrict__ W) {
    int idx = blockIdx.x * blockDim.x + threadIdx.x;   // 4*8*16*32 = 16384
    if (idx >= N_LAYERS * 8 * 16 * 32) return;
    int lane = idx & 31;
    int nfg  = (idx >> 5) & 15;
    int ks   = (idx >> 9) & 7;
    int l    = idx >> 12;
    int c  = nfg * 8 + (lane >> 2);
    int rk = ks * 16 + (lane & 3) * 2;
    const float* Wl = W + (size_t)l * D * D;
    float w00 = Wl[rk * D + c];
    float w01 = Wl[(rk + 1) * D + c];
    float w10 = Wl[(rk + 8) * D + c];
    float w11 = Wl[(rk + 9) * D + c];
    __nv_bfloat162 h, lo;
    uint4 out;
    h.x = __float2bfloat16_rn(w00); h.y = __float2bfloat16_rn(w01);
    lo.x = __float2bfloat16_rn(w00 - __bfloat162float(h.x));
    lo.y = __float2bfloat16_rn(w01 - __bfloat162float(h.y));
    out.x = *(uint32_t*)&h;
    out.z = *(uint32_t*)&lo;
    h.x = __float2bfloat16_rn(w10); h.y = __float2bfloat16_rn(w11);
    lo.x = __float2bfloat16_rn(w10 - __bfloat162float(h.x));
    lo.y = __float2bfloat16_rn(w11 - __bfloat162float(h.y));
    out.y = *(uint32_t*)&h;
    out.w = *(uint32_t*)&lo;
    g_wfrag[((size_t)l * 128 + ks * 16 + nfg) * 32 + lane] = out;
}

// permuted storage position of global pair index q (0..63):
// ks = q>>3; pos-in-group = (q&3)*2 + ((q>>2)&1)
__device__ __forceinline__ int pair_slot(int q) {
    return ((q >> 3) << 3) + ((q & 3) * 2) + ((q >> 2) & 1);
}

// ---------------- aggregation: warp per node (R7 loop body), permuted stores ----------------
__global__ void k_agg(const float* __restrict__ hin, int n) {
    int w = (blockIdx.x * blockDim.x + threadIdx.x) >> 5;
    int lane = threadIdx.x & 31;
    if (w >= n) return;
    int j0 = g_row_ptr[w];
    int j1 = g_row_ptr[w + 1];
    const float4* h4 = (const float4*)hin;
    float4 acc = make_float4(0.f, 0.f, 0.f, 0.f);
    for (int j = j0; j < j1; j++) {
        int s = g_col[j];
        float ns = g_norm_src[s];
        float4 v = __ldg(&h4[(size_t)s * 32 + lane]);
        acc.x = fmaf(ns, v.x, acc.x);
        acc.y = fmaf(ns, v.y, acc.y);
        acc.z = fmaf(ns, v.z, acc.z);
        acc.w = fmaf(ns, v.w, acc.w);
    }
    float nd = g_norm_dst[w];
    float ox = acc.x * nd, oy = acc.y * nd, oz = acc.z * nd, ow = acc.w * nd;
    __nv_bfloat162 h01, h23, l01, l23;
    h01.x = __float2bfloat16_rn(ox); h01.y = __float2bfloat16_rn(oy);
    h23.x = __float2bfloat16_rn(oz); h23.y = __float2bfloat16_rn(ow);
    l01.x = __float2bfloat16_rn(ox - __bfloat162float(h01.x));
    l01.y = __float2bfloat16_rn(oy - __bfloat162float(h01.y));
    l23.x = __float2bfloat16_rn(oz - __bfloat162float(h23.x));
    l23.y = __float2bfloat16_rn(ow - __bfloat162float(h23.y));
    int q0 = lane * 2, q1 = q0 + 1;
    size_t base = (size_t)w * 64;
    g_agg_hi[base + pair_slot(q0)] = *(uint32_t*)&h01;
    g_agg_hi[base + pair_slot(q1)] = *(uint32_t*)&h23;
    g_agg_lo[base + pair_slot(q0)] = *(uint32_t*)&l01;
    g_agg_lo[base + pair_slot(q1)] = *(uint32_t*)&l23;
}

// ---------------- GEMM via mma.sync bf16 (hi/lo split) ----------------
__device__ __forceinline__ void mma16816(float* d, uint32_t a0, uint32_t a1, uint32_t a2,
                                         uint32_t a3, uint32_t b0, uint32_t b1) {
    asm volatile(
        "mma.sync.aligned.m16n8k16.row.col.f32.bf16.bf16.f32 "
        "{%0,%1,%2,%3}, {%4,%5,%6,%7}, {%8,%9}, {%0,%1,%2,%3};"
        : "+f"(d[0]), "+f"(d[1]), "+f"(d[2]), "+f"(d[3])
        : "r"(a0), "r"(a1), "r"(a2), "r"(a3), "r"(b0), "r"(b1));
}

// CTA: 128 rows x 128 cols. 8 warps: 4 (M, 32 rows each) x 2 (N, 64 cols each).
__global__ void __launch_bounds__(256)
k_gemm_mma(const uint4* __restrict__ wfrag, const float* __restrict__ bias,
           float* __restrict__ C, int n) {
    int tid = threadIdx.x;
    int warp = tid >> 5, lane = tid & 31;
    int warp_m = warp & 3, warp_n = warp >> 2;
    int m_base = blockIdx.x * 128 + warp_m * 32;
    int n_base = warp_n * 64;
    int r0 = lane >> 2;          // 0..7
    int cp = lane & 3;           // col-pair index within fragment

    float d[2][8][4];
    #pragma unroll
    for (int mf = 0; mf < 2; mf++)
        #pragma unroll
        for (int nf = 0; nf < 8; nf++)
            #pragma unroll
            for (int j = 0; j < 4; j++) d[mf][nf][j] = 0.f;

    const uint2* hi2 = (const uint2*)g_agg_hi;
    const uint2* lo2 = (const uint2*)g_agg_lo;

    #pragma unroll
    for (int ks = 0; ks < 8; ks++) {
        uint2 AH0[2], AH1[2], AL0[2], AL1[2];
        #pragma unroll
        for (int mf = 0; mf < 2; mf++) {
            int row0 = m_base + mf * 16 + r0;
            int row1 = row0 + 8;
            bool v0 = row0 < n, v1 = row1 < n;
            size_t i0 = (size_t)row0 * 32 + ks * 4 + cp;
            size_t i1 = (size_t)row1 * 32 + ks * 4 + cp;
            AH0[mf] = v0 ? __ldg(&hi2[i0]) : make_uint2(0u, 0u);
            AH1[mf] = v1 ? __ldg(&hi2[i1]) : make_uint2(0u, 0u);
            AL0[mf] = v0 ? __ldg(&lo2[i0]) : make_uint2(0u, 0u);
            AL1[mf] = v1 ? __ldg(&lo2[i1]) : make_uint2(0u, 0u);
        }
        #pragma unroll
        for (int nf = 0; nf < 8; nf++) {
            uint4 w = __ldg(&wfrag[((size_t)ks * 16 + warp_n * 8 + nf) * 32 + lane]);
            #pragma unroll
            for (int mf = 0; mf < 2; mf++) {
                mma16816(d[mf][nf], AH0[mf].x, AH1[mf].x, AH0[mf].y, AH1[mf].y, w.x, w.y); // hi*hi
                mma16816(d[mf][nf], AH0[mf].x, AH1[mf].x, AH0[mf].y, AH1[mf].y, w.z, w.w); // hi*lo
                mma16816(d[mf][nf], AL0[mf].x, AL1[mf].x, AL0[mf].y, AL1[mf].y, w.x, w.y); // lo*hi
            }
        }
    }

    // Epilogue: bias add + store
    #pragma unroll
    for (int nf = 0; nf < 8; nf++) {
        int col = n_base + nf * 8 + cp * 2;
        float2 bb = *(const float2*)&bias[col];
        #pragma unroll
        for (int mf = 0; mf < 2; mf++) {
            int row0 = m_base + mf * 16 + r0;
            int row1 = row0 + 8;
            if (row0 < n) {
                float2 o = make_float2(d[mf][nf][0] + bb.x, d[mf][nf][1] + bb.y);
                *(float2*)&C[(size_t)row0 * 128 + col] = o;
            }
            if (row1 < n) {
                float2 o = make_float2(d[mf][nf][2] + bb.x, d[mf][nf][3] + bb.y);
                *(float2*)&C[(size_t)row1 * 128 + col] = o;
            }
        }
    }
}

// ---------------- host ----------------
extern "C" void kernel_launch(void* const* d_in, const int* in_sizes, int n_in,
                              void* d_out, int out_size) {
    const float* feat = (const float*)d_in[0];
    const float* W    = (const float*)d_in[1];
    const float* b    = (const float*)d_in[2];
    const int*   src  = (const int*)d_in[3];   // jax x64-off: int32
    const int*   dst  = (const int*)d_in[4];
    int N = in_sizes[0] / D;
    int E = in_sizes[3];

    float *h0, *h1;
    cudaGetSymbolAddress((void**)&h0, g_h0);
    cudaGetSymbolAddress((void**)&h1, g_h1);
    uint4* wfrag;
    cudaGetSymbolAddress((void**)&wfrag, g_wfrag);

    int nb = (N + 255) / 256;
    int eb = (E + 255) / 256;

    k_zero<<<nb, 256>>>(N);                                       // 0
    k_count<<<eb, 256>>>(src, dst, E);                            // 1
    k_scan<<<1, 1024>>>(N);                                       // 2 (scan + norms)
    k_fill<<<eb, 256>>>(src, dst, E);                             // 3
    k_prep_w<<<(N_LAYERS * 8 * 16 * 32 + 255) / 256, 256>>>(W);   // 4

    float* out = (float*)d_out;
    const float* hin = feat;
    int aggBlocks  = (N + 7) / 8;
    int gemmBlocks = (N + 127) / 128;

    for (int l = 0; l < N_LAYERS; l++) {                          // 5..12
        k_agg<<<aggBlocks, 256>>>(hin, N);
        float* hout = (l == N_LAYERS - 1) ? out : ((l & 1) ? h1 : h0);
        k_gemm_mma<<<gemmBlocks, 256>>>(wfrag + (size_t)l * 128 * 32,
                                        b + (size_t)l * D, hout, N);
        hin = hout;
    }
}